// round 17
// baseline (speedup 1.0000x reference)
#include <cuda_runtime.h>
#include <cuda_bf16.h>
#include <cuda_fp16.h>
#include <cstdint>
#include <cstddef>

// ---------------- problem constants ----------------
#define Tt      4
#define Bt      64
#define BpC     16
#define Cc      512
#define Nn      512
#define Hh      8
#define GD      64
#define TAU     0.5f
#define THRESH  1.0f
#define SCALE   0.125f
#define EPSBN   1e-5f
#define SZ      (Bt*Cc*Nn)      // 16,777,216
#define CN      (Cc*Nn)

typedef unsigned long long ull;

// ---------------- scratch (device globals) ----------------
__device__ __align__(128) __half g_spkh[3ll*SZ];      // [b][c][n]; plane 0 unused (q goes to g_qT)
__device__ __align__(128) __half g_qT  [SZ];          // q spikes fp16 [b][n][c]
__device__ __align__(128) __half g_P   [16*8*4*4096]; // P per (bp,h,t) fp16: 4 MB
__device__ __align__(128) __nv_bfloat16 g_xhi[SZ];    // [b][n][c]
__device__ __align__(128) __nv_bfloat16 g_xlo[SZ];
__device__ __align__(128) __half        g_s16[SZ];    // attn spikes fp16 [b][n][c]
__device__ __align__(128) __nv_bfloat16 g_whi[3ll*CN];
__device__ __align__(128) __nv_bfloat16 g_wlo[3ll*CN];
__device__ __align__(128) __half        g_wp16[CN];

// ---------------- PTX helpers ----------------
static __device__ __forceinline__ uint32_t smem_u32(const void* p) {
    uint32_t a;
    asm("{ .reg .u64 t; cvta.to.shared.u64 t, %1; cvt.u32.u64 %0, t; }" : "=r"(a) : "l"(p));
    return a;
}
static __device__ __forceinline__ void cpasync16(uint32_t dst, const void* src) {
    asm volatile("cp.async.cg.shared.global [%0], [%1], 16;" :: "r"(dst), "l"(src));
}
#define CP_COMMIT()  asm volatile("cp.async.commit_group;" ::: "memory")
#define CP_WAIT(n)   asm volatile("cp.async.wait_group %0;" :: "n"(n) : "memory")

static __device__ __forceinline__ void ldm_x4(uint32_t* r, uint32_t addr) {
    asm volatile("ldmatrix.sync.aligned.m8n8.x4.shared.b16 {%0,%1,%2,%3}, [%4];"
        : "=r"(r[0]), "=r"(r[1]), "=r"(r[2]), "=r"(r[3]) : "r"(addr));
}
static __device__ __forceinline__ void mma_bf16(float* c, const uint32_t* a, const uint32_t* b) {
    asm volatile("mma.sync.aligned.m16n8k16.row.col.f32.bf16.bf16.f32 "
        "{%0,%1,%2,%3}, {%4,%5,%6,%7}, {%8,%9}, {%0,%1,%2,%3};"
        : "+f"(c[0]), "+f"(c[1]), "+f"(c[2]), "+f"(c[3])
        : "r"(a[0]), "r"(a[1]), "r"(a[2]), "r"(a[3]), "r"(b[0]), "r"(b[1]));
}
static __device__ __forceinline__ void mma_f16(float* c, const uint32_t* a, const uint32_t* b) {
    asm volatile("mma.sync.aligned.m16n8k16.row.col.f32.f16.f16.f32 "
        "{%0,%1,%2,%3}, {%4,%5,%6,%7}, {%8,%9}, {%0,%1,%2,%3};"
        : "+f"(c[0]), "+f"(c[1]), "+f"(c[2]), "+f"(c[3])
        : "r"(a[0]), "r"(a[1]), "r"(a[2]), "r"(a[3]), "r"(b[0]), "r"(b[1]));
}

// =====================================================================
// weight split: qkv -> bf16 hi/lo; proj -> fp16 single
// =====================================================================
__global__ __launch_bounds__(256) void wsplit_kernel(
    const float* __restrict__ wq, const float* __restrict__ wk,
    const float* __restrict__ wv, const float* __restrict__ wp)
{
    const int which = blockIdx.y;
    const float* w = (which == 0) ? wq : (which == 1) ? wk : (which == 2) ? wv : wp;
    const int i = blockIdx.x * 256 + threadIdx.x;
    float v = w[i];
    if (which < 3) {
        __nv_bfloat16 h = __float2bfloat16(v);
        g_whi[(size_t)which * CN + i] = h;
        g_wlo[(size_t)which * CN + i] = __float2bfloat16(v - __bfloat162float(h));
    } else {
        g_wp16[i] = __float2half(v);
    }
}

// =====================================================================
// x transpose + split: fp32 [b][c][n] -> bf16 hi/lo [b][n][c]
// =====================================================================
__global__ __launch_bounds__(256) void split_t_kernel(const float* __restrict__ in)
{
    __shared__ float t[32][33];
    const int b = blockIdx.z, c0 = blockIdx.y * 32, n0 = blockIdx.x * 32;
    const int tx = threadIdx.x, ty = threadIdx.y;
    const float* ib = in + (size_t)b * CN;
    #pragma unroll
    for (int j = 0; j < 4; j++)
        t[ty + 8*j][tx] = ib[(size_t)(c0 + ty + 8*j) * Nn + n0 + tx];
    __syncthreads();
    #pragma unroll
    for (int j = 0; j < 4; j++) {
        const int n = ty + 8*j;
        const float v = t[tx][n];
        const size_t o = ((size_t)b * Nn + n0 + n) * Cc + c0 + tx;
        const __nv_bfloat16 h = __float2bfloat16(v);
        g_xhi[o] = h;
        g_xlo[o] = __float2bfloat16(v - __bfloat162float(h));
    }
}

// =====================================================================
// qkv HMMA conv_bn + FUSED LIF, FLAT (t,kc) PIPELINE (no per-t drain).
// grid (4, 12, 16 bp). wsel==0 epilogue writes q spikes TRANSPOSED to
// g_qT [b][n][c]; wsel 1,2 write [b][c][n] to g_spkh.
// =====================================================================
#define ROWB   144
#define TILEB  (128*ROWB)
#define STAGEB (4*TILEB)

__global__ __launch_bounds__(256) void hmma_conv_lif(
    const float* __restrict__ bng, const float* __restrict__ bnb,
    const float* __restrict__ bnm, const float* __restrict__ bnv)
{
    extern __shared__ char smem[];
    const uint32_t sb = smem_u32(smem);
    const int tid  = threadIdx.x;
    const int wid  = tid >> 5, lane = tid & 31;
    const int n0   = blockIdx.x * 128;
    const int bp   = blockIdx.z;
    const int wsel = blockIdx.y >> 2;
    const int r0   = (blockIdx.y & 3) * 128;

    const __nv_bfloat16* wh = g_whi + (size_t)wsel * CN + (size_t)r0 * Cc;
    const __nv_bfloat16* wl = g_wlo + (size_t)wsel * CN + (size_t)r0 * Cc;

    const int lrow = tid >> 1;
    const int cb0  = (tid & 1) * 4;
    const uint32_t rowOff = (uint32_t)lrow * ROWB;
    const __nv_bfloat16* gAh = wh + (size_t)lrow * Cc;
    const __nv_bfloat16* gAl = wl + (size_t)lrow * Cc;

    // per-t B pointers
    const __nv_bfloat16* bhp[4];
    const __nv_bfloat16* blp[4];
    #pragma unroll
    for (int t = 0; t < 4; t++) {
        const int b = t*BpC + bp;
        bhp[t] = g_xhi + ((size_t)b * Nn + n0) * Cc + (size_t)lrow * Cc;
        blp[t] = g_xlo + ((size_t)b * Nn + n0) * Cc + (size_t)lrow * Cc;
    }

    const int wm = wid & 1, wn = wid >> 1;
    const int grp = lane >> 3, wi = lane & 7;

    float invA[4], biasA[4], invB[4], biasB[4];
    #pragma unroll
    for (int mi = 0; mi < 4; mi++) {
        const int rA = r0 + wm*64 + mi*16 + (lane >> 2);
        const int rB = rA + 8;
        invA[mi]  = bng[wsel*Cc + rA] / sqrtf(bnv[wsel*Cc + rA] + EPSBN);
        biasA[mi] = bnb[wsel*Cc + rA] - bnm[wsel*Cc + rA] * invA[mi];
        invB[mi]  = bng[wsel*Cc + rB] / sqrtf(bnv[wsel*Cc + rB] + EPSBN);
        biasB[mi] = bnb[wsel*Cc + rB] - bnm[wsel*Cc + rB] * invB[mi];
    }

    float mem[4][4][4];
    float acc[4][4][4];
    #pragma unroll
    for (int i = 0; i < 4; i++)
        #pragma unroll
        for (int j = 0; j < 4; j++)
            #pragma unroll
            for (int q = 0; q < 4; q++) { mem[i][j][q] = 0.f; acc[i][j][q] = 0.f; }

    auto load_stage = [&](uint32_t st, int t, int k0) {
        #pragma unroll
        for (int j = 0; j < 4; j++) {
            const int c = cb0 + j;
            const uint32_t off = rowOff + c * 16;
            cpasync16(st + off,           gAh + k0 + c*8);
            cpasync16(st + TILEB + off,   gAl + k0 + c*8);
            cpasync16(st + 2*TILEB + off, bhp[t] + k0 + c*8);
            cpasync16(st + 3*TILEB + off, blp[t] + k0 + c*8);
        }
    };

    load_stage(sb, 0, 0);
    CP_COMMIT();

    for (int it = 0; it < 32; it++) {
        const int t = it >> 3, kc = it & 7, s = it & 1;
        if (it < 31) {
            load_stage(sb + (s^1)*STAGEB, (it+1) >> 3, ((it+1) & 7) * 64);
            CP_COMMIT();
            CP_WAIT(1);
        } else {
            CP_WAIT(0);
        }
        __syncthreads();

        const uint32_t st = sb + s * STAGEB;
        #pragma unroll
        for (int ks = 0; ks < 4; ks++) {
            uint32_t Ah[4][4], Al[4][4], Bh[4][2], Bl[4][2];
            #pragma unroll
            for (int mi = 0; mi < 4; mi++) {
                const uint32_t ra = st
                    + (uint32_t)(wm*64 + mi*16 + wi + (grp&1)*8) * ROWB
                    + (uint32_t)(ks*32 + (grp>>1)*16);
                ldm_x4(Ah[mi], ra);
                ldm_x4(Al[mi], ra + TILEB);
            }
            #pragma unroll
            for (int bt = 0; bt < 2; bt++) {
                const uint32_t rb = st + 2*TILEB
                    + (uint32_t)(wn*32 + bt*16 + wi + (grp>>1)*8) * ROWB
                    + (uint32_t)(ks*32 + (grp&1)*16);
                uint32_t r[4];
                ldm_x4(r, rb);
                Bh[bt*2][0] = r[0]; Bh[bt*2][1] = r[1];
                Bh[bt*2+1][0] = r[2]; Bh[bt*2+1][1] = r[3];
                ldm_x4(r, rb + TILEB);
                Bl[bt*2][0] = r[0]; Bl[bt*2][1] = r[1];
                Bl[bt*2+1][0] = r[2]; Bl[bt*2+1][1] = r[3];
            }
            #pragma unroll
            for (int mi = 0; mi < 4; mi++)
                #pragma unroll
                for (int nt = 0; nt < 4; nt++)
                    mma_bf16(acc[mi][nt], Ah[mi], Bh[nt]);
            #pragma unroll
            for (int mi = 0; mi < 4; mi++)
                #pragma unroll
                for (int nt = 0; nt < 4; nt++)
                    mma_bf16(acc[mi][nt], Al[mi], Bh[nt]);
            #pragma unroll
            for (int mi = 0; mi < 4; mi++)
                #pragma unroll
                for (int nt = 0; nt < 4; nt++)
                    mma_bf16(acc[mi][nt], Ah[mi], Bl[nt]);
        }

        if (kc == 7) {
            // BN + LIF epilogue for timestep t, then reset acc
            const int b = t*BpC + bp;
            #pragma unroll
            for (int mi = 0; mi < 4; mi++) {
                const int rA = r0 + wm*64 + mi*16 + (lane >> 2);
                const int rB = rA + 8;
                #pragma unroll
                for (int nt = 0; nt < 4; nt++) {
                    const int nc = wn*32 + nt*8 + (lane & 3)*2;
                    float pre[4];
                    pre[0] = acc[mi][nt][0]*invA[mi] + biasA[mi];
                    pre[1] = acc[mi][nt][1]*invA[mi] + biasA[mi];
                    pre[2] = acc[mi][nt][2]*invB[mi] + biasB[mi];
                    pre[3] = acc[mi][nt][3]*invB[mi] + biasB[mi];
                    float sp[4];
                    #pragma unroll
                    for (int q = 0; q < 4; q++) {
                        mem[mi][nt][q] = mem[mi][nt][q]*TAU + pre[q];
                        sp[q] = (mem[mi][nt][q] > THRESH) ? 1.f : 0.f;
                        if (mem[mi][nt][q] > THRESH) mem[mi][nt][q] = 0.f;
                        acc[mi][nt][q] = 0.f;
                    }
                    if (wsel == 0) {
                        // q spikes: write TRANSPOSED to g_qT [b][n][c]
                        __half* q0 = g_qT + ((size_t)b*Nn + n0 + nc)     * Cc;
                        __half* q1 = g_qT + ((size_t)b*Nn + n0 + nc + 1) * Cc;
                        q0[rA] = __float2half(sp[0]);
                        q1[rA] = __float2half(sp[1]);
                        q0[rB] = __float2half(sp[2]);
                        q1[rB] = __float2half(sp[3]);
                    } else {
                        __half* spkb = g_spkh + (size_t)wsel * SZ;
                        __half* pA = spkb + ((size_t)b * Cc + rA) * Nn + n0;
                        __half* pB = spkb + ((size_t)b * Cc + rB) * Nn + n0;
                        *(__half2*)&pA[nc] = __floats2half2_rn(sp[0], sp[1]);
                        *(__half2*)&pB[nc] = __floats2half2_rn(sp[2], sp[3]);
                    }
                }
            }
        }
        __syncthreads();
    }
}

// =====================================================================
// proj conv_bn: fp16 SINGLE-term. grid (4, 4, 64), 2 CTAs/SM
// =====================================================================
#define PTILE  (128*ROWB)               // 18432
#define PSTG   (2*PTILE)                // 36864
#define PROJ_SMEM (2*PSTG)              // 73728

__global__ __launch_bounds__(256, 2) void proj_conv(
    float* __restrict__ extout,
    const float* __restrict__ bng, const float* __restrict__ bnb,
    const float* __restrict__ bnm, const float* __restrict__ bnv)
{
    extern __shared__ char smem[];
    const uint32_t sb = smem_u32(smem);
    const int tid  = threadIdx.x;
    const int wid  = tid >> 5, lane = tid & 31;
    const int n0   = blockIdx.x * 128;
    const int r0   = blockIdx.y * 128;
    const int b    = blockIdx.z;

    const __half* wp = g_wp16 + (size_t)r0 * Cc;
    const __half* sp = g_s16 + ((size_t)b * Nn + n0) * Cc;

    const int lrow = tid >> 1;
    const int cb0  = (tid & 1) * 4;
    const uint32_t rowOff = (uint32_t)lrow * ROWB;
    const __half* gA = wp + (size_t)lrow * Cc;
    const __half* gB = sp + (size_t)lrow * Cc;

    float acc[4][4][4];
    #pragma unroll
    for (int i = 0; i < 4; i++)
        #pragma unroll
        for (int j = 0; j < 4; j++)
            #pragma unroll
            for (int q = 0; q < 4; q++) acc[i][j][q] = 0.f;

    const int wm = wid & 1, wn = wid >> 1;
    const int grp = lane >> 3, wi = lane & 7;

    auto load_stage = [&](uint32_t st, int k0) {
        #pragma unroll
        for (int j = 0; j < 4; j++) {
            const int c = cb0 + j;
            const uint32_t off = rowOff + c * 16;
            cpasync16(st + off,         gA + k0 + c*8);
            cpasync16(st + PTILE + off, gB + k0 + c*8);
        }
    };

    load_stage(sb, 0);
    CP_COMMIT();

    for (int kc = 0; kc < 8; kc++) {
        const int s = kc & 1;
        if (kc < 7) {
            load_stage(sb + (s^1)*PSTG, (kc + 1) * 64);
            CP_COMMIT();
            CP_WAIT(1);
        } else {
            CP_WAIT(0);
        }
        __syncthreads();

        const uint32_t st = sb + s * PSTG;
        #pragma unroll
        for (int ks = 0; ks < 4; ks++) {
            uint32_t A[4][4], B[4][2];
            #pragma unroll
            for (int mi = 0; mi < 4; mi++) {
                const uint32_t ra = st
                    + (uint32_t)(wm*64 + mi*16 + wi + (grp&1)*8) * ROWB
                    + (uint32_t)(ks*32 + (grp>>1)*16);
                ldm_x4(A[mi], ra);
            }
            #pragma unroll
            for (int bt = 0; bt < 2; bt++) {
                const uint32_t rb = st + PTILE
                    + (uint32_t)(wn*32 + bt*16 + wi + (grp>>1)*8) * ROWB
                    + (uint32_t)(ks*32 + (grp&1)*16);
                uint32_t r[4];
                ldm_x4(r, rb);
                B[bt*2][0] = r[0]; B[bt*2][1] = r[1];
                B[bt*2+1][0] = r[2]; B[bt*2+1][1] = r[3];
            }
            #pragma unroll
            for (int mi = 0; mi < 4; mi++)
                #pragma unroll
                for (int nt = 0; nt < 4; nt++)
                    mma_f16(acc[mi][nt], A[mi], B[nt]);
        }
        __syncthreads();
    }

    #pragma unroll
    for (int mi = 0; mi < 4; mi++) {
        const int rA = r0 + wm*64 + mi*16 + (lane >> 2);
        const int rB = rA + 8;
        const float invA  = bng[3*Cc + rA] / sqrtf(bnv[3*Cc + rA] + EPSBN);
        const float biasA = bnb[3*Cc + rA] - bnm[3*Cc + rA] * invA;
        const float invB  = bng[3*Cc + rB] / sqrtf(bnv[3*Cc + rB] + EPSBN);
        const float biasB = bnb[3*Cc + rB] - bnm[3*Cc + rB] * invB;
        float* pA = extout + ((size_t)b * Cc + rA) * Nn + n0;
        float* pB = extout + ((size_t)b * Cc + rB) * Nn + n0;
        #pragma unroll
        for (int nt = 0; nt < 4; nt++) {
            const int nc = wn*32 + nt*8 + (lane & 3)*2;
            float2 v0, v1;
            v0.x = acc[mi][nt][0]*invA + biasA;
            v0.y = acc[mi][nt][1]*invA + biasA;
            v1.x = acc[mi][nt][2]*invB + biasB;
            v1.y = acc[mi][nt][3]*invB + biasB;
            *(float2*)&pA[nc] = v0;
            *(float2*)&pB[nc] = v1;
        }
    }
}

// =====================================================================
// attn_m_h: P = V·K^T (64x64, inner 512) per (bp, h, t), fp16 HMMA (exact)
// =====================================================================
#define MROWB  144
#define MTILE  (64*MROWB)       // 9216

__global__ __launch_bounds__(256) void attn_m_h()
{
    __shared__ __align__(16) char smem[4*MTILE];     // 2 stages x (V|K)
    const uint32_t sb = smem_u32(smem);
    const int bp = blockIdx.x, h = blockIdx.y, t = blockIdx.z;
    const int tid = threadIdx.x;
    const int wid = tid >> 5, lane = tid & 31;
    const int b = t*BpC + bp;

    const __half* V = g_spkh + (size_t)2*SZ + ((size_t)b*Cc + h*GD) * Nn;
    const __half* K = g_spkh + (size_t)SZ   + ((size_t)b*Cc + h*GD) * Nn;

    const int lrow = tid >> 2;
    const int cq2  = (tid & 3) * 2;
    const uint32_t rowOff = (uint32_t)lrow * MROWB;
    const __half* gV = V + (size_t)lrow * Nn;
    const __half* gK = K + (size_t)lrow * Nn;

    const int wm = wid & 1, wn = wid >> 1;
    const int grp = lane >> 3, wi = lane & 7;

    float acc[2][2][4];
    #pragma unroll
    for (int i = 0; i < 2; i++)
        #pragma unroll
        for (int j = 0; j < 2; j++)
            #pragma unroll
            for (int q = 0; q < 4; q++) acc[i][j][q] = 0.f;

    auto load_stage = [&](uint32_t st, int k0) {
        #pragma unroll
        for (int j = 0; j < 2; j++) {
            const int c = cq2 + j;
            const uint32_t off = rowOff + c * 16;
            cpasync16(st + off,         gV + k0 + c*8);
            cpasync16(st + MTILE + off, gK + k0 + c*8);
        }
    };

    load_stage(sb, 0);
    CP_COMMIT();

    for (int kc = 0; kc < 8; kc++) {
        const int s = kc & 1;
        if (kc < 7) {
            load_stage(sb + (s^1)*2*MTILE, (kc + 1) * 64);
            CP_COMMIT();
            CP_WAIT(1);
        } else {
            CP_WAIT(0);
        }
        __syncthreads();

        const uint32_t st = sb + s*2*MTILE;
        #pragma unroll
        for (int ks = 0; ks < 4; ks++) {
            uint32_t A[2][4], B[2][2];
            #pragma unroll
            for (int mi = 0; mi < 2; mi++) {
                const uint32_t ra = st
                    + (uint32_t)(wm*32 + mi*16 + wi + (grp&1)*8) * MROWB
                    + (uint32_t)(ks*32 + (grp>>1)*16);
                ldm_x4(A[mi], ra);
            }
            {
                const uint32_t rb = st + MTILE
                    + (uint32_t)(wn*16 + wi + (grp>>1)*8) * MROWB
                    + (uint32_t)(ks*32 + (grp&1)*16);
                uint32_t r[4];
                ldm_x4(r, rb);
                B[0][0] = r[0]; B[0][1] = r[1];
                B[1][0] = r[2]; B[1][1] = r[3];
            }
            #pragma unroll
            for (int mi = 0; mi < 2; mi++)
                #pragma unroll
                for (int nt = 0; nt < 2; nt++)
                    mma_f16(acc[mi][nt], A[mi], B[nt]);
        }
        __syncthreads();
    }

    __half* Pout = g_P + (((size_t)(bp*Hh + h) * 4) + t) * 4096;
    #pragma unroll
    for (int mi = 0; mi < 2; mi++) {
        const int rA = wm*32 + mi*16 + (lane >> 2);
        const int rB = rA + 8;
        #pragma unroll
        for (int nt = 0; nt < 2; nt++) {
            const int nc = wn*16 + nt*8 + (lane & 3)*2;
            *(__half2*)&Pout[rA*64 + nc] = __floats2half2_rn(acc[mi][nt][0], acc[mi][nt][1]);
            *(__half2*)&Pout[rB*64 + nc] = __floats2half2_rn(acc[mi][nt][2], acc[mi][nt][3]);
        }
    }
}

// =====================================================================
// attn_out_h (swapped): out^T[n][d] = Σ_dk Q^T[n][dk]·P_t[d][dk], + LIF,
// writes spikes directly to g_s16 [b][n][c]. grid (16, 8, 4 nq)
// =====================================================================
#define AOUT_SMEM (4*MTILE + 128*MROWB)   // 55296

__global__ __launch_bounds__(256) void attn_out_h()
{
    extern __shared__ char smem[];
    const uint32_t sb = smem_u32(smem);
    const uint32_t Ps = sb;
    const uint32_t Qs = sb + 4*MTILE;

    const int bp = blockIdx.x, h = blockIdx.y, nq = blockIdx.z;
    const int tid = threadIdx.x;
    const int wid = tid >> 5, lane = tid & 31;
    const int wm = wid & 3, wn = wid >> 2;
    const int grp = lane >> 3, wi = lane & 7;

    {
        const __half* Pin = g_P + ((size_t)(bp*Hh + h) * 4) * 4096;
        #pragma unroll
        for (int j = 0; j < 8; j++) {
            const int cid = tid*8 + j;
            const int tt = cid >> 9, row = (cid >> 3) & 63, c = cid & 7;
            cpasync16(Ps + tt*MTILE + row*MROWB + c*16, Pin + tt*4096 + row*64 + c*8);
        }
        CP_COMMIT();
    }

    const int qrow = tid >> 1;
    const int qc0  = (tid & 1) * 4;

    float mem[2][4][4];
    #pragma unroll
    for (int i = 0; i < 2; i++)
        #pragma unroll
        for (int j = 0; j < 4; j++)
            #pragma unroll
            for (int q = 0; q < 4; q++) mem[i][j][q] = 0.f;

    for (int t = 0; t < 4; t++) {
        const int b = t*BpC + bp;
        const __half* Qt = g_qT + ((size_t)b * Nn + nq*128 + qrow) * Cc + h*GD;
        #pragma unroll
        for (int j = 0; j < 4; j++) {
            const int c = qc0 + j;
            cpasync16(Qs + qrow*MROWB + c*16, Qt + c*8);
        }
        CP_COMMIT(); CP_WAIT(0);
        __syncthreads();

        float acc[2][4][4];
        #pragma unroll
        for (int i = 0; i < 2; i++)
            #pragma unroll
            for (int j = 0; j < 4; j++)
                #pragma unroll
                for (int q = 0; q < 4; q++) acc[i][j][q] = 0.f;

        #pragma unroll
        for (int ks = 0; ks < 4; ks++) {
            uint32_t A[2][4], B[4][2];
            #pragma unroll
            for (int mi = 0; mi < 2; mi++) {
                const uint32_t ra = Qs
                    + (uint32_t)(wm*32 + mi*16 + wi + (grp&1)*8) * MROWB
                    + (uint32_t)(ks*32 + (grp>>1)*16);
                ldm_x4(A[mi], ra);
            }
            #pragma unroll
            for (int bt = 0; bt < 2; bt++) {
                const uint32_t rb = Ps + t*MTILE
                    + (uint32_t)(wn*32 + bt*16 + wi + (grp>>1)*8) * MROWB
                    + (uint32_t)(ks*32 + (grp&1)*16);
                uint32_t r[4];
                ldm_x4(r, rb);
                B[bt*2][0] = r[0]; B[bt*2][1] = r[1];
                B[bt*2+1][0] = r[2]; B[bt*2+1][1] = r[3];
            }
            #pragma unroll
            for (int mi = 0; mi < 2; mi++)
                #pragma unroll
                for (int nt = 0; nt < 4; nt++)
                    mma_f16(acc[mi][nt], A[mi], B[nt]);
        }

        #pragma unroll
        for (int mi = 0; mi < 2; mi++) {
            const int nA = nq*128 + wm*32 + mi*16 + (lane >> 2);
            const int nB = nA + 8;
            __half* pA = g_s16 + ((size_t)b*Nn + nA) * Cc + h*GD;
            __half* pB = g_s16 + ((size_t)b*Nn + nB) * Cc + h*GD;
            #pragma unroll
            for (int nt = 0; nt < 4; nt++) {
                const int dc = wn*32 + nt*8 + (lane & 3)*2;
                float o[4];
                o[0] = acc[mi][nt][0]*SCALE; o[1] = acc[mi][nt][1]*SCALE;
                o[2] = acc[mi][nt][2]*SCALE; o[3] = acc[mi][nt][3]*SCALE;
                float s[4];
                #pragma unroll
                for (int q = 0; q < 4; q++) {
                    mem[mi][nt][q] = mem[mi][nt][q]*TAU + o[q];
                    s[q] = (mem[mi][nt][q] > THRESH) ? 1.f : 0.f;
                    if (mem[mi][nt][q] > THRESH) mem[mi][nt][q] = 0.f;
                }
                *(__half2*)&pA[dc] = __floats2half2_rn(s[0], s[1]);
                *(__half2*)&pB[dc] = __floats2half2_rn(s[2], s[3]);
            }
        }
        __syncthreads();
    }
}

// =====================================================================
// launch
// =====================================================================
extern "C" void kernel_launch(void* const* d_in, const int* in_sizes, int n_in,
                              void* d_out, int out_size)
{
    const float* x     = (const float*)d_in[0];
    const float* wq    = (const float*)d_in[1];
    const float* wk    = (const float*)d_in[2];
    const float* wv    = (const float*)d_in[3];
    const float* wproj = (const float*)d_in[4];
    const float* bng   = (const float*)d_in[5];
    const float* bnb   = (const float*)d_in[6];
    const float* bnm   = (const float*)d_in[7];
    const float* bnv   = (const float*)d_in[8];
    float* out = (float*)d_out;

    const int conv_smem = 2 * STAGEB;   // 147,456 B
    cudaFuncSetAttribute(hmma_conv_lif, cudaFuncAttributeMaxDynamicSharedMemorySize, conv_smem);
    cudaFuncSetAttribute(proj_conv, cudaFuncAttributeMaxDynamicSharedMemorySize, PROJ_SMEM);
    cudaFuncSetAttribute(attn_out_h, cudaFuncAttributeMaxDynamicSharedMemorySize, AOUT_SMEM);

    wsplit_kernel<<<dim3(1024, 4), 256>>>(wq, wk, wv, wproj);
    split_t_kernel<<<dim3(16, 16, 64), dim3(32, 8)>>>(x);

    // merged q,k,v conv_bn + fused LIF (flat t-pipeline; q written transposed)
    hmma_conv_lif<<<dim3(4, 12, 16), 256, conv_smem>>>(bng, bnb, bnm, bnv);

    // attention on tensor pipe (exact fp16); out written directly [b][n][c]
    attn_m_h<<<dim3(BpC, Hh, 4), 256>>>();
    attn_out_h<<<dim3(BpC, Hh, 4), 256, AOUT_SMEM>>>();

    // proj conv_bn (fp16 single-term)
    proj_conv<<<dim3(4, 4, 64), 256, PROJ_SMEM>>>(out, bng, bnb, bnm, bnv);
}